// round 13
// baseline (speedup 1.0000x reference)
#include <cuda_runtime.h>
#include <math.h>

#define B_ 32
#define N_ 4096
#define KS_ 1024
#define D_ 1024
#define H_ 16
#define MAXF_ 4096
#define CTXM (B_*H_*D_)

// ---------------- scratch (device globals; no allocation) ----------------
__device__ float g_q[B_*2*D_];
__device__ float g_x[B_*2*D_];
__device__ float g_qn[B_*2*D_];
__device__ float g_qkv[B_*2*3*D_];
__device__ float g_attn[B_*2*D_];
__device__ float g_qp[B_*D_];
__device__ float g_qkd[B_*H_*D_];
__device__ float g_S[(size_t)B_*H_*N_];
__device__ float g_ctx[4][CTXM];
__device__ float g_op[B_*D_];
__device__ float g_ffn[B_*2*4*D_];
__device__ float g_mp[4][B_*D_];

// ---------------- partial mean over N (4 k-segments) ----------------
__global__ void k_meanpart(const float* __restrict__ frame) {
    int b = blockIdx.x, dc = blockIdx.y, ks = blockIdx.z;
    int d = dc * 256 + threadIdx.x;
    const float* p = frame + ((size_t)b * N_ + (size_t)ks * (N_ / 4)) * D_ + d;
    float s = 0.f;
#pragma unroll 8
    for (int k = 0; k < N_ / 4; k++) s += p[(size_t)k * D_];
    g_mp[ks][b * D_ + d] = s;
}

// ---------------- q init ----------------
__global__ void k_qinit(const float* __restrict__ max_init,
                        const float* __restrict__ qbase,
                        const float* __restrict__ role,
                        const float* __restrict__ timew,
                        const int* __restrict__ fidx) {
    int b = blockIdx.x;
    int d = blockIdx.y * 256 + threadIdx.x;
    int fi = fidx[b];
    fi = fi < 0 ? 0 : (fi > MAXF_ - 1 ? MAXF_ - 1 : fi);
    float te = timew[(size_t)fi * D_ + d];
    float mean = (g_mp[0][b * D_ + d] + g_mp[1][b * D_ + d] +
                  g_mp[2][b * D_ + d] + g_mp[3][b * D_ + d]) * (1.f / N_);
    g_q[(size_t)(b * 2 + 0) * D_ + d] = mean + qbase[d] + role[d] + te;
    g_q[(size_t)(b * 2 + 1) * D_ + d] = max_init[(size_t)b * D_ + d] + qbase[D_ + d] + role[D_ + d] + te;
}

// ---------------- layernorm (one block per row) ----------------
__global__ void k_ln(const float* __restrict__ in, float* __restrict__ out,
                     const float* __restrict__ g, const float* __restrict__ bta) {
    __shared__ float sh[8];
    __shared__ float stat[2];
    int r = blockIdx.x;
    const float* x = in + (size_t)r * D_;
    float s = 0.f;
    for (int i = threadIdx.x; i < D_; i += 256) s += x[i];
#pragma unroll
    for (int o = 16; o > 0; o >>= 1) s += __shfl_xor_sync(0xffffffffu, s, o);
    if ((threadIdx.x & 31) == 0) sh[threadIdx.x >> 5] = s;
    __syncthreads();
    if (threadIdx.x == 0) {
        float t = 0.f;
        for (int i = 0; i < 8; i++) t += sh[i];
        stat[0] = t * (1.f / D_);
    }
    __syncthreads();
    float mean = stat[0];
    float v = 0.f;
    for (int i = threadIdx.x; i < D_; i += 256) { float t = x[i] - mean; v += t * t; }
#pragma unroll
    for (int o = 16; o > 0; o >>= 1) v += __shfl_xor_sync(0xffffffffu, v, o);
    if ((threadIdx.x & 31) == 0) sh[threadIdx.x >> 5] = v;
    __syncthreads();
    if (threadIdx.x == 0) {
        float t = 0.f;
        for (int i = 0; i < 8; i++) t += sh[i];
        stat[1] = rsqrtf(t * (1.f / D_) + 1e-5f);
    }
    __syncthreads();
    float rstd = stat[1];
    for (int i = threadIdx.x; i < D_; i += 256)
        out[(size_t)r * D_ + i] = (x[i] - mean) * rstd * g[i] + bta[i];
}

// ---------------- generic small GEMM: out[r,c] = act(sum_k A[r,k]*W[c,k] + bias[c])
// 256 thr; tile 32 cols x 32 rows; grid = (C/32, R/32)
__global__ void k_gemm(const float* __restrict__ A, int lda,
                       const float* __restrict__ W, const float* __restrict__ bias,
                       float* __restrict__ out, int ldo,
                       int Kdim, int act, int accflag) {
    __shared__ float sW[32][33];
    __shared__ float sA[32][36];
    int col_l = threadIdx.x & 31;
    int rg = threadIdx.x >> 5;          // 0..7
    int c = blockIdx.x * 32 + col_l;
    int r0 = blockIdx.y * 32;
    float accv[4] = {0.f, 0.f, 0.f, 0.f};
    int lw_c = threadIdx.x >> 3;        // 0..31
    int lw_k = (threadIdx.x & 7) * 4;   // 0,4,..,28
    for (int k0 = 0; k0 < Kdim; k0 += 32) {
        __syncthreads();
        float4 wv = *(const float4*)&W[(size_t)(blockIdx.x * 32 + lw_c) * Kdim + k0 + lw_k];
        sW[lw_c][lw_k + 0] = wv.x; sW[lw_c][lw_k + 1] = wv.y;
        sW[lw_c][lw_k + 2] = wv.z; sW[lw_c][lw_k + 3] = wv.w;
        float4 av = *(const float4*)&A[(size_t)(r0 + lw_c) * lda + k0 + lw_k];
        sA[lw_k + 0][lw_c] = av.x; sA[lw_k + 1][lw_c] = av.y;
        sA[lw_k + 2][lw_c] = av.z; sA[lw_k + 3][lw_c] = av.w;
        __syncthreads();
#pragma unroll
        for (int k = 0; k < 32; k++) {
            float w = sW[col_l][k];
            float4 a = *(const float4*)&sA[k][rg * 4];
            accv[0] = fmaf(a.x, w, accv[0]);
            accv[1] = fmaf(a.y, w, accv[1]);
            accv[2] = fmaf(a.z, w, accv[2]);
            accv[3] = fmaf(a.w, w, accv[3]);
        }
    }
    float bv = bias[c];
#pragma unroll
    for (int i = 0; i < 4; i++) {
        float v = accv[i] + bv;
        if (act == 1) v = 0.5f * v * (1.f + erff(v * 0.70710678118654752f));
        float* o = &out[(size_t)(r0 + rg * 4 + i) * ldo + c];
        if (accflag) *o += v; else *o = v;
    }
}

// ---------------- self-attention over 2 tokens: one warp per (b,h) ----------
__global__ void k_selfattn() {
    int b = blockIdx.x, h = blockIdx.y, lane = threadIdx.x;
    const float* row0 = g_qkv + (size_t)(b * 2 + 0) * 3072;
    const float* row1 = g_qkv + (size_t)(b * 2 + 1) * 3072;
    int off = h * 64 + lane * 2;
    float2 q0 = *(const float2*)(row0 + off);
    float2 q1 = *(const float2*)(row1 + off);
    float2 kk0 = *(const float2*)(row0 + 1024 + off);
    float2 kk1 = *(const float2*)(row1 + 1024 + off);
    float2 v0 = *(const float2*)(row0 + 2048 + off);
    float2 v1 = *(const float2*)(row1 + 2048 + off);
    float s00 = q0.x * kk0.x + q0.y * kk0.y;
    float s01 = q0.x * kk1.x + q0.y * kk1.y;
    float s10 = q1.x * kk0.x + q1.y * kk0.y;
    float s11 = q1.x * kk1.x + q1.y * kk1.y;
#pragma unroll
    for (int o = 16; o > 0; o >>= 1) {
        s00 += __shfl_xor_sync(0xffffffffu, s00, o);
        s01 += __shfl_xor_sync(0xffffffffu, s01, o);
        s10 += __shfl_xor_sync(0xffffffffu, s10, o);
        s11 += __shfl_xor_sync(0xffffffffu, s11, o);
    }
    s00 *= 0.125f; s01 *= 0.125f; s10 *= 0.125f; s11 *= 0.125f;
    float m0 = fmaxf(s00, s01), m1 = fmaxf(s10, s11);
    float e00 = expf(s00 - m0), e01 = expf(s01 - m0);
    float e10 = expf(s10 - m1), e11 = expf(s11 - m1);
    float i0 = 1.f / (e00 + e01), i1 = 1.f / (e10 + e11);
    float a00 = e00 * i0, a01 = e01 * i0, a10 = e10 * i1, a11 = e11 * i1;
    float2 o0, o1;
    o0.x = a00 * v0.x + a01 * v1.x; o0.y = a00 * v0.y + a01 * v1.y;
    o1.x = a10 * v0.x + a11 * v1.x; o1.y = a10 * v0.y + a11 * v1.y;
    *(float2*)(g_attn + (size_t)(b * 2 + 0) * D_ + off) = o0;
    *(float2*)(g_attn + (size_t)(b * 2 + 1) * D_ + off) = o1;
}

// ---------------- qkdir[b,h,:] = sum_j qp[b,h*64+j] * wk[h*64+j,:] ----------
__global__ void k_qkdir(const float* __restrict__ qp, const float* __restrict__ wk) {
    int h = blockIdx.x;
    int d = blockIdx.y * 256 + threadIdx.x;
    int b0 = blockIdx.z * 8;
    __shared__ float sqp[8][64];
    for (int i = threadIdx.x; i < 512; i += 256) {
        int bb = i >> 6, j = i & 63;
        sqp[bb][j] = qp[(size_t)(b0 + bb) * D_ + h * 64 + j];
    }
    __syncthreads();
    float acc[8] = {0.f, 0.f, 0.f, 0.f, 0.f, 0.f, 0.f, 0.f};
    const float* wp = wk + (size_t)(h * 64) * D_ + d;
#pragma unroll 4
    for (int j = 0; j < 64; j++) {
        float w = wp[(size_t)j * D_];
#pragma unroll
        for (int bb = 0; bb < 8; bb++) acc[bb] = fmaf(sqp[bb][j], w, acc[bb]);
    }
#pragma unroll
    for (int bb = 0; bb < 8; bb++)
        g_qkd[(size_t)((b0 + bb) * H_ + h) * D_ + d] = acc[bb];
}

// ---------------- scores: S[b,h,k] = 0.125 * qkdir[b,h].f[b,k] ----------
// grid (Nk/256, B); block 256; thread tile 4 heads x 4 keys
__global__ void k_scores(const float* __restrict__ f, int Nk) {
    int b = blockIdx.y;
    int k0 = blockIdx.x * 256;
    int tx = threadIdx.x;
    int hg = tx >> 6;          // 0..3
    int kg = tx & 63;          // 0..63
    __shared__ float sf[32][260];
    __shared__ float sqk[32][20];
    float acc[4][4];
#pragma unroll
    for (int i = 0; i < 4; i++)
#pragma unroll
        for (int j = 0; j < 4; j++) acc[i][j] = 0.f;
    const float* fb = f + ((size_t)b * Nk + k0) * D_;
    const float* qb = g_qkd + (size_t)b * H_ * D_;
    for (int d0 = 0; d0 < D_; d0 += 32) {
        __syncthreads();
        for (int e = tx; e < 512; e += 256) {
            int h = e >> 5, d = e & 31;
            sqk[d][h] = qb[(size_t)h * D_ + d0 + d];
        }
#pragma unroll
        for (int r = 0; r < 8; r++) {
            int e = r * 1024 + tx * 4;
            int key = e >> 5;
            int dd = e & 31;
            float4 v = *(const float4*)(fb + (size_t)key * D_ + d0 + dd);
            sf[dd + 0][key] = v.x; sf[dd + 1][key] = v.y;
            sf[dd + 2][key] = v.z; sf[dd + 3][key] = v.w;
        }
        __syncthreads();
#pragma unroll
        for (int d = 0; d < 32; d++) {
            float4 q4 = *(const float4*)&sqk[d][hg * 4];
            float4 f4 = *(const float4*)&sf[d][kg * 4];
            acc[0][0] = fmaf(q4.x, f4.x, acc[0][0]); acc[0][1] = fmaf(q4.x, f4.y, acc[0][1]);
            acc[0][2] = fmaf(q4.x, f4.z, acc[0][2]); acc[0][3] = fmaf(q4.x, f4.w, acc[0][3]);
            acc[1][0] = fmaf(q4.y, f4.x, acc[1][0]); acc[1][1] = fmaf(q4.y, f4.y, acc[1][1]);
            acc[1][2] = fmaf(q4.y, f4.z, acc[1][2]); acc[1][3] = fmaf(q4.y, f4.w, acc[1][3]);
            acc[2][0] = fmaf(q4.z, f4.x, acc[2][0]); acc[2][1] = fmaf(q4.z, f4.y, acc[2][1]);
            acc[2][2] = fmaf(q4.z, f4.z, acc[2][2]); acc[2][3] = fmaf(q4.z, f4.w, acc[2][3]);
            acc[3][0] = fmaf(q4.w, f4.x, acc[3][0]); acc[3][1] = fmaf(q4.w, f4.y, acc[3][1]);
            acc[3][2] = fmaf(q4.w, f4.z, acc[3][2]); acc[3][3] = fmaf(q4.w, f4.w, acc[3][3]);
        }
    }
#pragma unroll
    for (int i = 0; i < 4; i++)
#pragma unroll
        for (int j = 0; j < 4; j++)
            g_S[((size_t)b * H_ + hg * 4 + i) * Nk + k0 + kg * 4 + j] = acc[i][j] * 0.125f;
}

// ---------------- softmax over Nk per (b,h) row ----------
__global__ void k_softmax(int Nk) {
    __shared__ float sh[8];
    __shared__ float stat;
    int tx = threadIdx.x;
    float* s = g_S + (size_t)blockIdx.x * Nk;
    float m = -1e30f;
    for (int i = tx; i < Nk; i += 256) m = fmaxf(m, s[i]);
#pragma unroll
    for (int o = 16; o > 0; o >>= 1) m = fmaxf(m, __shfl_xor_sync(0xffffffffu, m, o));
    if ((tx & 31) == 0) sh[tx >> 5] = m;
    __syncthreads();
    if (tx == 0) {
        float t = sh[0];
        for (int i = 1; i < 8; i++) t = fmaxf(t, sh[i]);
        stat = t;
    }
    __syncthreads();
    m = stat;
    float sum = 0.f;
    for (int i = tx; i < Nk; i += 256) {
        float e = expf(s[i] - m);
        s[i] = e;
        sum += e;
    }
#pragma unroll
    for (int o = 16; o > 0; o >>= 1) sum += __shfl_xor_sync(0xffffffffu, sum, o);
    if ((tx & 31) == 0) sh[tx >> 5] = sum;
    __syncthreads();
    if (tx == 0) {
        float t = 0.f;
        for (int i = 0; i < 8; i++) t += sh[i];
        stat = 1.f / t;
    }
    __syncthreads();
    float inv = stat;
    for (int i = tx; i < Nk; i += 256) s[i] *= inv;
}

// ---------------- context: ctx[b,h,d] = sum_k a[b,h,k]*f[b,k,d] (ksplit 4) ----
// grid (D/256, B, 4); block 256; thread tile 4 heads x 4 d
__global__ void k_context(const float* __restrict__ f, int Nk) {
    int d0 = blockIdx.x * 256;
    int b = blockIdx.y;
    int part = blockIdx.z;
    int kn = Nk >> 2;
    int kbase = part * kn;
    int tx = threadIdx.x;
    int hg = tx >> 6;
    int dg = tx & 63;
    __shared__ float sf[32][260];
    __shared__ float sa[32][20];
    float acc[4][4];
#pragma unroll
    for (int i = 0; i < 4; i++)
#pragma unroll
        for (int j = 0; j < 4; j++) acc[i][j] = 0.f;
    const float* fb = f + ((size_t)b * Nk + kbase) * D_ + d0;
    const float* ab = g_S + (size_t)b * H_ * Nk + kbase;
    for (int kc = 0; kc < kn; kc += 32) {
        __syncthreads();
        for (int e = tx; e < 512; e += 256) {
            int h = e >> 5, k = e & 31;
            sa[k][h] = ab[(size_t)h * Nk + kc + k];
        }
#pragma unroll
        for (int r = 0; r < 8; r++) {
            int e = r * 1024 + tx * 4;
            int k = e >> 8;
            int dd = e & 255;
            float4 v = *(const float4*)(fb + (size_t)(kc + k) * D_ + dd);
            *(float4*)&sf[k][dd] = v;
        }
        __syncthreads();
#pragma unroll
        for (int k = 0; k < 32; k++) {
            float4 a4 = *(const float4*)&sa[k][hg * 4];
            float4 f4 = *(const float4*)&sf[k][dg * 4];
            acc[0][0] = fmaf(a4.x, f4.x, acc[0][0]); acc[0][1] = fmaf(a4.x, f4.y, acc[0][1]);
            acc[0][2] = fmaf(a4.x, f4.z, acc[0][2]); acc[0][3] = fmaf(a4.x, f4.w, acc[0][3]);
            acc[1][0] = fmaf(a4.y, f4.x, acc[1][0]); acc[1][1] = fmaf(a4.y, f4.y, acc[1][1]);
            acc[1][2] = fmaf(a4.y, f4.z, acc[1][2]); acc[1][3] = fmaf(a4.y, f4.w, acc[1][3]);
            acc[2][0] = fmaf(a4.z, f4.x, acc[2][0]); acc[2][1] = fmaf(a4.z, f4.y, acc[2][1]);
            acc[2][2] = fmaf(a4.z, f4.z, acc[2][2]); acc[2][3] = fmaf(a4.z, f4.w, acc[2][3]);
            acc[3][0] = fmaf(a4.w, f4.x, acc[3][0]); acc[3][1] = fmaf(a4.w, f4.y, acc[3][1]);
            acc[3][2] = fmaf(a4.w, f4.z, acc[3][2]); acc[3][3] = fmaf(a4.w, f4.w, acc[3][3]);
        }
    }
#pragma unroll
    for (int i = 0; i < 4; i++)
#pragma unroll
        for (int j = 0; j < 4; j++)
            g_ctx[part][(size_t)(b * H_ + hg * 4 + i) * D_ + d0 + dg * 4 + j] = acc[i][j];
}

// ---------------- vproj: o[b, h*64+j] = bv + sum_d wv[h*64+j,d]*ctx[b,h,d] ----
// grid (D/32); block 256; tile 32 cols x 32 b
__global__ void k_vproj(const float* __restrict__ wv, const float* __restrict__ bv) {
    int c0 = blockIdx.x * 32;
    int h = c0 >> 6;
    int tx = threadIdx.x;
    int col_l = tx & 31, bg = tx >> 5;
    __shared__ float sW[32][33];
    __shared__ float sC[32][36];
    float acc[4] = {0.f, 0.f, 0.f, 0.f};
    int lw_c = tx >> 3, lw_k = (tx & 7) * 4;
    for (int d0 = 0; d0 < D_; d0 += 32) {
        __syncthreads();
        float4 w4 = *(const float4*)&wv[(size_t)(c0 + lw_c) * D_ + d0 + lw_k];
        sW[lw_c][lw_k + 0] = w4.x; sW[lw_c][lw_k + 1] = w4.y;
        sW[lw_c][lw_k + 2] = w4.z; sW[lw_c][lw_k + 3] = w4.w;
#pragma unroll
        for (int r = 0; r < 4; r++) {
            int e = r * 256 + tx;
            int bb = e >> 5, d = e & 31;
            size_t idx = (size_t)(bb * H_ + h) * D_ + d0 + d;
            sC[d][bb] = g_ctx[0][idx] + g_ctx[1][idx] + g_ctx[2][idx] + g_ctx[3][idx];
        }
        __syncthreads();
#pragma unroll
        for (int d = 0; d < 32; d++) {
            float w = sW[col_l][d];
            float4 c4 = *(const float4*)&sC[d][bg * 4];
            acc[0] = fmaf(w, c4.x, acc[0]);
            acc[1] = fmaf(w, c4.y, acc[1]);
            acc[2] = fmaf(w, c4.z, acc[2]);
            acc[3] = fmaf(w, c4.w, acc[3]);
        }
    }
    float bias = bv[c0 + col_l];
#pragma unroll
    for (int i = 0; i < 4; i++)
        g_op[(size_t)(bg * 4 + i) * D_ + c0 + col_l] = acc[i] + bias;
}

// ==================== host ====================
static float* devptr(const void* sym) {
    void* p = nullptr;
    cudaGetSymbolAddress(&p, (const void*)sym);
    return (float*)p;
}

extern "C" void kernel_launch(void* const* d_in, const int* in_sizes, int n_in,
                              void* d_out, int out_size) {
    const float* frame    = (const float*)d_in[0];
    const float* kvsal    = (const float*)d_in[1];
    const float* max_init = (const float*)d_in[2];
    const float* qbase    = (const float*)d_in[3];
    const float* role     = (const float*)d_in[4];
    const float* timew    = (const float*)d_in[5];
    const float* ln1_g = (const float*)d_in[6],  *ln1_b = (const float*)d_in[7];
    const float* sa_in_w = (const float*)d_in[8],  *sa_in_b = (const float*)d_in[9];
    const float* sa_out_w = (const float*)d_in[10], *sa_out_b = (const float*)d_in[11];
    const float* ln2_g = (const float*)d_in[12], *ln2_b = (const float*)d_in[13];
    const float* cg_in_w = (const float*)d_in[14], *cg_in_b = (const float*)d_in[15];
    const float* cg_out_w = (const float*)d_in[16], *cg_out_b = (const float*)d_in[17];
    const float* cs_in_w = (const float*)d_in[18], *cs_in_b = (const float*)d_in[19];
    const float* cs_out_w = (const float*)d_in[20], *cs_out_b = (const float*)d_in[21];
    const float* ln3_g = (const float*)d_in[22], *ln3_b = (const float*)d_in[23];
    const float* ffn_w1 = (const float*)d_in[24], *ffn_b1 = (const float*)d_in[25];
    const float* ffn_w2 = (const float*)d_in[26], *ffn_b2 = (const float*)d_in[27];
    const float* out_g = (const float*)d_in[28], *out_b = (const float*)d_in[29];
    const int* fidx = (const int*)d_in[30];
    float* out = (float*)d_out;

    float* dq    = devptr(g_q);
    float* dx    = devptr(g_x);
    float* dqn   = devptr(g_qn);
    float* dqkv  = devptr(g_qkv);
    float* dattn = devptr(g_attn);
    float* dqp   = devptr(g_qp);
    float* dop   = devptr(g_op);
    float* dffn  = devptr(g_ffn);

    // ---- init ----
    k_meanpart<<<dim3(B_, 4, 4), 256>>>(frame);
    k_qinit<<<dim3(B_, 4), 256>>>(max_init, qbase, role, timew, fidx);

    for (int l = 0; l < 2; l++) {
        const float* saw  = sa_in_w  + (size_t)l * 3 * D_ * D_;
        const float* sab  = sa_in_b  + (size_t)l * 3 * D_;
        const float* saow = sa_out_w + (size_t)l * D_ * D_;
        const float* saob = sa_out_b + (size_t)l * D_;

        // --- self-attention block ---
        k_ln<<<64, 256>>>(dq, dx, ln1_g + l * D_, ln1_b + l * D_);
        k_gemm<<<dim3(96, 2), 256>>>(dx, D_, saw, sab, dqkv, 3 * D_, D_, 0, 0);
        k_selfattn<<<dim3(B_, H_), 32>>>();
        k_gemm<<<dim3(32, 2), 256>>>(dattn, D_, saow, saob, dq, D_, D_, 0, 1);

        // --- LN2 ---
        k_ln<<<64, 256>>>(dq, dqn, ln2_g + l * D_, ln2_b + l * D_);

        // --- cross-attention stream A (token 0, frame_tokens, N=4096) ---
        {
            const float* cw  = cg_in_w  + (size_t)l * 3 * D_ * D_;
            const float* cb  = cg_in_b  + (size_t)l * 3 * D_;
            const float* cow = cg_out_w + (size_t)l * D_ * D_;
            const float* cob = cg_out_b + (size_t)l * D_;
            k_gemm<<<dim3(32, 1), 256>>>(dqn, 2 * D_, cw, cb, dqp, D_, D_, 0, 0);
            k_qkdir<<<dim3(H_, 4, 4), 256>>>(dqp, cw + (size_t)D_ * D_);
            k_scores<<<dim3(N_ / 256, B_), 256>>>(frame, N_);
            k_softmax<<<B_ * H_, 256>>>(N_);
            k_context<<<dim3(4, B_, 4), 256>>>(frame, N_);
            k_vproj<<<32, 256>>>(cw + (size_t)2 * D_ * D_, cb + 2 * D_);
            k_gemm<<<dim3(32, 1), 256>>>(dop, D_, cow, cob, dq, 2 * D_, D_, 0, 1);
        }
        // --- cross-attention stream B (token 1, kv_salient, K=1024) ---
        {
            const float* cw  = cs_in_w  + (size_t)l * 3 * D_ * D_;
            const float* cb  = cs_in_b  + (size_t)l * 3 * D_;
            const float* cow = cs_out_w + (size_t)l * D_ * D_;
            const float* cob = cs_out_b + (size_t)l * D_;
            k_gemm<<<dim3(32, 1), 256>>>(dqn + D_, 2 * D_, cw, cb, dqp, D_, D_, 0, 0);
            k_qkdir<<<dim3(H_, 4, 4), 256>>>(dqp, cw + (size_t)D_ * D_);
            k_scores<<<dim3(KS_ / 256, B_), 256>>>(kvsal, KS_);
            k_softmax<<<B_ * H_, 256>>>(KS_);
            k_context<<<dim3(4, B_, 4), 256>>>(kvsal, KS_);
            k_vproj<<<32, 256>>>(cw + (size_t)2 * D_ * D_, cb + 2 * D_);
            k_gemm<<<dim3(32, 1), 256>>>(dop, D_, cow, cob, dq + D_, 2 * D_, D_, 0, 1);
        }

        // --- FFN ---
        k_ln<<<64, 256>>>(dq, dx, ln3_g + l * D_, ln3_b + l * D_);
        k_gemm<<<dim3(128, 2), 256>>>(dx, D_, ffn_w1 + (size_t)l * 4 * D_ * D_,
                                      ffn_b1 + (size_t)l * 4 * D_, dffn, 4 * D_, D_, 1, 0);
        k_gemm<<<dim3(32, 2), 256>>>(dffn, 4 * D_, ffn_w2 + (size_t)l * 4 * D_ * D_,
                                     ffn_b2 + (size_t)l * D_, dq, D_, 4 * D_, 0, 1);
    }

    // ---- final LN ----
    k_ln<<<64, 256>>>(dq, out, out_g, out_b);
}

// round 15
// speedup vs baseline: 1.1237x; 1.1237x over previous
#include <cuda_runtime.h>
#include <math.h>

#define B_ 32
#define N_ 4096
#define KS_ 1024
#define D_ 1024
#define H_ 16
#define MAXF_ 4096
#define CTXM (B_*H_*D_)

typedef unsigned long long u64;

__device__ __forceinline__ void fma2(u64 &d, u64 a, u64 b) {
    asm("fma.rn.f32x2 %0,%1,%2,%0;" : "+l"(d) : "l"(a), "l"(b));
}
__device__ __forceinline__ void lds128(u64 &a, u64 &b, const void* p) {
    unsigned s = (unsigned)__cvta_generic_to_shared(p);
    asm("ld.shared.v2.u64 {%0,%1},[%2];" : "=l"(a), "=l"(b) : "r"(s));
}
__device__ __forceinline__ float2 unpk(u64 v) {
    float2 r; asm("mov.b64 {%0,%1},%2;" : "=f"(r.x), "=f"(r.y) : "l"(v)); return r;
}

// ---------------- scratch (device globals; no allocation) ----------------
__device__ float g_q[B_*2*D_];
__device__ float g_x[B_*2*D_];
__device__ float g_qn[B_*2*D_];
__device__ float g_qkv[B_*2*3*D_];
__device__ float g_attn[B_*2*D_];
__device__ float g_qp[B_*D_];
__device__ float g_qkd[B_*H_*D_];
__device__ float g_S[(size_t)B_*H_*N_];
__device__ float g_ctx[4][CTXM];
__device__ float g_op[B_*D_];
__device__ float g_ffn[B_*2*4*D_];
__device__ float g_mp[4][B_*D_];
__device__ float g_part[2*1024*1024];

// ---------------- partial mean over N (4 k-segments) ----------------
__global__ void k_meanpart(const float* __restrict__ frame) {
    int b = blockIdx.x, dc = blockIdx.y, ks = blockIdx.z;
    int d = dc * 256 + threadIdx.x;
    const float* p = frame + ((size_t)b * N_ + (size_t)ks * (N_ / 4)) * D_ + d;
    float s = 0.f;
#pragma unroll 8
    for (int k = 0; k < N_ / 4; k++) s += p[(size_t)k * D_];
    g_mp[ks][b * D_ + d] = s;
}

// ---------------- q init ----------------
__global__ void k_qinit(const float* __restrict__ max_init,
                        const float* __restrict__ qbase,
                        const float* __restrict__ role,
                        const float* __restrict__ timew,
                        const int* __restrict__ fidx) {
    int b = blockIdx.x;
    int d = blockIdx.y * 256 + threadIdx.x;
    int fi = fidx[b];
    fi = fi < 0 ? 0 : (fi > MAXF_ - 1 ? MAXF_ - 1 : fi);
    float te = timew[(size_t)fi * D_ + d];
    float mean = (g_mp[0][b * D_ + d] + g_mp[1][b * D_ + d] +
                  g_mp[2][b * D_ + d] + g_mp[3][b * D_ + d]) * (1.f / N_);
    g_q[(size_t)(b * 2 + 0) * D_ + d] = mean + qbase[d] + role[d] + te;
    g_q[(size_t)(b * 2 + 1) * D_ + d] = max_init[(size_t)b * D_ + d] + qbase[D_ + d] + role[D_ + d] + te;
}

// ---------------- layernorm (one block per row) ----------------
__global__ void k_ln(const float* __restrict__ in, float* __restrict__ out,
                     const float* __restrict__ g, const float* __restrict__ bta) {
    __shared__ float sh[8];
    __shared__ float stat[2];
    int r = blockIdx.x;
    const float* x = in + (size_t)r * D_;
    float s = 0.f;
    for (int i = threadIdx.x; i < D_; i += 256) s += x[i];
#pragma unroll
    for (int o = 16; o > 0; o >>= 1) s += __shfl_xor_sync(0xffffffffu, s, o);
    if ((threadIdx.x & 31) == 0) sh[threadIdx.x >> 5] = s;
    __syncthreads();
    if (threadIdx.x == 0) {
        float t = 0.f;
        for (int i = 0; i < 8; i++) t += sh[i];
        stat[0] = t * (1.f / D_);
    }
    __syncthreads();
    float mean = stat[0];
    float v = 0.f;
    for (int i = threadIdx.x; i < D_; i += 256) { float t = x[i] - mean; v += t * t; }
#pragma unroll
    for (int o = 16; o > 0; o >>= 1) v += __shfl_xor_sync(0xffffffffu, v, o);
    if ((threadIdx.x & 31) == 0) sh[threadIdx.x >> 5] = v;
    __syncthreads();
    if (threadIdx.x == 0) {
        float t = 0.f;
        for (int i = 0; i < 8; i++) t += sh[i];
        stat[1] = rsqrtf(t * (1.f / D_) + 1e-5f);
    }
    __syncthreads();
    float rstd = stat[1];
    for (int i = threadIdx.x; i < D_; i += 256)
        out[(size_t)r * D_ + i] = (x[i] - mean) * rstd * g[i] + bta[i];
}

// ---------------- split-K skinny GEMM: part[z,r,c] = sum_{k in slice z} A[r,k]*W[c,k]
// grid = (C/32, rowsTot/32, Z); block 256
__global__ void __launch_bounds__(256) k_gemmKS(
        const float* __restrict__ A, int lda,
        const float* __restrict__ W, int Ktot,
        float* __restrict__ part, int C, int rowsTot, int Kslice) {
    __shared__ float sW[32][33];
    __shared__ float sA[32][36];
    int z = blockIdx.z;
    int col_l = threadIdx.x & 31;
    int rg = threadIdx.x >> 5;          // 0..7
    int c = blockIdx.x * 32 + col_l;
    int r0 = blockIdx.y * 32;
    float accv[4] = {0.f, 0.f, 0.f, 0.f};
    int lw_c = threadIdx.x >> 3;        // 0..31
    int lw_k = (threadIdx.x & 7) * 4;   // 0,4,..,28
    int kstart = z * Kslice;
    for (int k0 = kstart; k0 < kstart + Kslice; k0 += 32) {
        __syncthreads();
        float4 wv = *(const float4*)&W[(size_t)(blockIdx.x * 32 + lw_c) * Ktot + k0 + lw_k];
        sW[lw_c][lw_k + 0] = wv.x; sW[lw_c][lw_k + 1] = wv.y;
        sW[lw_c][lw_k + 2] = wv.z; sW[lw_c][lw_k + 3] = wv.w;
        float4 av = *(const float4*)&A[(size_t)(r0 + lw_c) * lda + k0 + lw_k];
        sA[lw_k + 0][lw_c] = av.x; sA[lw_k + 1][lw_c] = av.y;
        sA[lw_k + 2][lw_c] = av.z; sA[lw_k + 3][lw_c] = av.w;
        __syncthreads();
#pragma unroll
        for (int k = 0; k < 32; k++) {
            float w = sW[col_l][k];
            float4 a = *(const float4*)&sA[k][rg * 4];
            accv[0] = fmaf(a.x, w, accv[0]);
            accv[1] = fmaf(a.y, w, accv[1]);
            accv[2] = fmaf(a.z, w, accv[2]);
            accv[3] = fmaf(a.w, w, accv[3]);
        }
    }
#pragma unroll
    for (int i = 0; i < 4; i++)
        part[((size_t)(z * rowsTot + r0 + rg * 4 + i)) * C + c] = accv[i];
}

// ---------------- GEMM epilogue: sum Z partials + bias (+gelu) (+residual) ----
__global__ void k_gemmEp(int Z, int rowsTot, int C,
                         const float* __restrict__ bias,
                         float* __restrict__ out, int ldo, int act, int accflag) {
    int idx = blockIdx.x * 256 + threadIdx.x;
    if (idx >= rowsTot * C) return;
    int r = idx / C, c = idx - r * C;
    float s = 0.f;
    for (int z = 0; z < Z; z++) s += g_part[((size_t)(z * rowsTot + r)) * C + c];
    s += bias[c];
    if (act == 1) s = 0.5f * s * (1.f + erff(s * 0.70710678118654752f));
    float* o = &out[(size_t)r * ldo + c];
    if (accflag) *o += s; else *o = s;
}

// ---------------- self-attention over 2 tokens: one warp per (b,h) ----------
__global__ void k_selfattn() {
    int b = blockIdx.x, h = blockIdx.y, lane = threadIdx.x;
    const float* row0 = g_qkv + (size_t)(b * 2 + 0) * 3072;
    const float* row1 = g_qkv + (size_t)(b * 2 + 1) * 3072;
    int off = h * 64 + lane * 2;
    float2 q0 = *(const float2*)(row0 + off);
    float2 q1 = *(const float2*)(row1 + off);
    float2 kk0 = *(const float2*)(row0 + 1024 + off);
    float2 kk1 = *(const float2*)(row1 + 1024 + off);
    float2 v0 = *(const float2*)(row0 + 2048 + off);
    float2 v1 = *(const float2*)(row1 + 2048 + off);
    float s00 = q0.x * kk0.x + q0.y * kk0.y;
    float s01 = q0.x * kk1.x + q0.y * kk1.y;
    float s10 = q1.x * kk0.x + q1.y * kk0.y;
    float s11 = q1.x * kk1.x + q1.y * kk1.y;
#pragma unroll
    for (int o = 16; o > 0; o >>= 1) {
        s00 += __shfl_xor_sync(0xffffffffu, s00, o);
        s01 += __shfl_xor_sync(0xffffffffu, s01, o);
        s10 += __shfl_xor_sync(0xffffffffu, s10, o);
        s11 += __shfl_xor_sync(0xffffffffu, s11, o);
    }
    s00 *= 0.125f; s01 *= 0.125f; s10 *= 0.125f; s11 *= 0.125f;
    float m0 = fmaxf(s00, s01), m1 = fmaxf(s10, s11);
    float e00 = expf(s00 - m0), e01 = expf(s01 - m0);
    float e10 = expf(s10 - m1), e11 = expf(s11 - m1);
    float i0 = 1.f / (e00 + e01), i1 = 1.f / (e10 + e11);
    float a00 = e00 * i0, a01 = e01 * i0, a10 = e10 * i1, a11 = e11 * i1;
    float2 o0, o1;
    o0.x = a00 * v0.x + a01 * v1.x; o0.y = a00 * v0.y + a01 * v1.y;
    o1.x = a10 * v0.x + a11 * v1.x; o1.y = a10 * v0.y + a11 * v1.y;
    *(float2*)(g_attn + (size_t)(b * 2 + 0) * D_ + off) = o0;
    *(float2*)(g_attn + (size_t)(b * 2 + 1) * D_ + off) = o1;
}

// ---------------- qkdir[b,h,:] = sum_j qp[b,h*64+j] * wk[h*64+j,:] ----------
__global__ void k_qkdir(const float* __restrict__ qp, const float* __restrict__ wk) {
    int h = blockIdx.x;
    int d = blockIdx.y * 256 + threadIdx.x;
    int b0 = blockIdx.z * 8;
    __shared__ float sqp[8][64];
    for (int i = threadIdx.x; i < 512; i += 256) {
        int bb = i >> 6, j = i & 63;
        sqp[bb][j] = qp[(size_t)(b0 + bb) * D_ + h * 64 + j];
    }
    __syncthreads();
    float acc[8] = {0.f, 0.f, 0.f, 0.f, 0.f, 0.f, 0.f, 0.f};
    const float* wp = wk + (size_t)(h * 64) * D_ + d;
#pragma unroll 4
    for (int j = 0; j < 64; j++) {
        float w = wp[(size_t)j * D_];
#pragma unroll
        for (int bb = 0; bb < 8; bb++) acc[bb] = fmaf(sqp[bb][j], w, acc[bb]);
    }
#pragma unroll
    for (int bb = 0; bb < 8; bb++)
        g_qkd[(size_t)((b0 + bb) * H_ + h) * D_ + d] = acc[bb];
}

// ---------------- scores (FFMA2, packed over d-parity) ----------------
// grid (Nk/128, B); block 128; thread = 8 heads x 2 keys
__global__ void __launch_bounds__(128) k_scores(const float* __restrict__ f, int Nk) {
    __shared__ float sf[128][36];
    __shared__ float sq[16][36];
    int b = blockIdx.y;
    int k0 = blockIdx.x * 128;
    int tx = threadIdx.x;
    int hg = tx >> 6;          // 0..1 -> heads hg*8..+7
    int kg = tx & 63;          // keys kg, kg+64
    u64 acc[8][2];
#pragma unroll
    for (int i = 0; i < 8; i++) { acc[i][0] = 0ull; acc[i][1] = 0ull; }
    const float* fb = f + ((size_t)b * Nk + k0) * D_;
    const float* qb = g_qkd + (size_t)b * H_ * D_;
    for (int d0 = 0; d0 < D_; d0 += 32) {
        __syncthreads();
        for (int e = tx; e < 512; e += 128) {
            int h = e >> 5, d = e & 31;
            sq[h][d] = qb[(size_t)h * D_ + d0 + d];
        }
#pragma unroll
        for (int r = 0; r < 8; r++) {
            int e = r * 128 + tx;
            int key = e >> 3;
            int dd = (e & 7) * 4;
            *(float4*)&sf[key][dd] = *(const float4*)(fb + (size_t)key * D_ + d0 + dd);
        }
        __syncthreads();
#pragma unroll
        for (int dp = 0; dp < 8; dp++) {
            int d = dp * 4;
            u64 f00, f01, f10, f11;
            lds128(f00, f01, &sf[kg][d]);
            lds128(f10, f11, &sf[kg + 64][d]);
#pragma unroll
            for (int hh = 0; hh < 8; hh++) {
                u64 q0, q1;
                lds128(q0, q1, &sq[hg * 8 + hh][d]);
                fma2(acc[hh][0], q0, f00); fma2(acc[hh][0], q1, f01);
                fma2(acc[hh][1], q0, f10); fma2(acc[hh][1], q1, f11);
            }
        }
    }
#pragma unroll
    for (int hh = 0; hh < 8; hh++) {
        int h = hg * 8 + hh;
        float2 t0 = unpk(acc[hh][0]);
        float2 t1 = unpk(acc[hh][1]);
        g_S[((size_t)b * H_ + h) * Nk + k0 + kg]      = (t0.x + t0.y) * 0.125f;
        g_S[((size_t)b * H_ + h) * Nk + k0 + kg + 64] = (t1.x + t1.y) * 0.125f;
    }
}

// ---------------- softmax over Nk per (b,h) row ----------
__global__ void k_softmax(int Nk) {
    __shared__ float sh[8];
    __shared__ float stat;
    int tx = threadIdx.x;
    float* s = g_S + (size_t)blockIdx.x * Nk;
    float m = -1e30f;
    for (int i = tx; i < Nk; i += 256) m = fmaxf(m, s[i]);
#pragma unroll
    for (int o = 16; o > 0; o >>= 1) m = fmaxf(m, __shfl_xor_sync(0xffffffffu, m, o));
    if ((tx & 31) == 0) sh[tx >> 5] = m;
    __syncthreads();
    if (tx == 0) {
        float t = sh[0];
        for (int i = 1; i < 8; i++) t = fmaxf(t, sh[i]);
        stat = t;
    }
    __syncthreads();
    m = stat;
    float sum = 0.f;
    for (int i = tx; i < Nk; i += 256) {
        float e = expf(s[i] - m);
        s[i] = e;
        sum += e;
    }
#pragma unroll
    for (int o = 16; o > 0; o >>= 1) sum += __shfl_xor_sync(0xffffffffu, sum, o);
    if ((tx & 31) == 0) sh[tx >> 5] = sum;
    __syncthreads();
    if (tx == 0) {
        float t = 0.f;
        for (int i = 0; i < 8; i++) t += sh[i];
        stat = 1.f / t;
    }
    __syncthreads();
    float inv = stat;
    for (int i = tx; i < Nk; i += 256) s[i] *= inv;
}

// ---------------- context (FFMA2, packed over output d) ----------------
// grid (D/256, B, 4 parts); block 128; thread = 8 heads x 4 d
__global__ void __launch_bounds__(128) k_context(const float* __restrict__ f, int Nk) {
    __shared__ float sf[32][260];
    __shared__ float2 sad[32][16];
    int d0 = blockIdx.x * 256;
    int b = blockIdx.y;
    int part = blockIdx.z;
    int kn = Nk >> 2;
    int kbase = part * kn;
    int tx = threadIdx.x;
    int hg = tx >> 6;          // 0..1 -> heads hg*8..+7
    int dg = tx & 63;          // d = dg*4..+3
    u64 acc[8][2];
#pragma unroll
    for (int i = 0; i < 8; i++) { acc[i][0] = 0ull; acc[i][1] = 0ull; }
    const float* fb = f + ((size_t)b * Nk + kbase) * D_ + d0;
    const float* ab = g_S + (size_t)b * H_ * Nk + kbase;
    for (int kc = 0; kc < kn; kc += 32) {
        __syncthreads();
        for (int e = tx; e < 512; e += 128) {
            int h = e >> 5, k = e & 31;
            float a = ab[(size_t)h * Nk + kc + k];
            sad[k][h] = make_float2(a, a);
        }
#pragma unroll
        for (int r = 0; r < 16; r++) {
            int e = r * 128 + tx;
            int k = e >> 6;
            int dd = (e & 63) * 4;
            *(float4*)&sf[k][dd] = *(const float4*)(fb + (size_t)(kc + k) * D_ + dd);
        }
        __syncthreads();
#pragma unroll
        for (int kk = 0; kk < 32; kk++) {
            u64 fv0, fv1;
            lds128(fv0, fv1, &sf[kk][dg * 4]);
            u64 ad[8];
            lds128(ad[0], ad[1], &sad[kk][hg * 8 + 0]);
            lds128(ad[2], ad[3], &sad[kk][hg * 8 + 2]);
            lds128(ad[4], ad[5], &sad[kk][hg * 8 + 4]);
            lds128(ad[6], ad[7], &sad[kk][hg * 8 + 6]);
#pragma unroll
            for (int hh = 0; hh < 8; hh++) {
                fma2(acc[hh][0], ad[hh], fv0);
                fma2(acc[hh][1], ad[hh], fv1);
            }
        }
    }
#pragma unroll
    for (int hh = 0; hh < 8; hh++) {
        int h = hg * 8 + hh;
        size_t idx = (size_t)(b * H_ + h) * D_ + d0 + dg * 4;
        *(u64*)&g_ctx[part][idx] = acc[hh][0];
        *(u64*)&g_ctx[part][idx + 2] = acc[hh][1];
    }
}

// ---------------- vproj: o[b, h*64+j] = bv + sum_d wv[h*64+j,d]*ctx[b,h,d] ----
__global__ void k_vproj(const float* __restrict__ wv, const float* __restrict__ bv) {
    int c0 = blockIdx.x * 32;
    int h = c0 >> 6;
    int tx = threadIdx.x;
    int col_l = tx & 31, bg = tx >> 5;
    __shared__ float sW[32][33];
    __shared__ float sC[32][36];
    float acc[4] = {0.f, 0.f, 0.f, 0.f};
    int lw_c = tx >> 3, lw_k = (tx & 7) * 4;
    for (int d0 = 0; d0 < D_; d0 += 32) {
        __syncthreads();
        float4 w4 = *(const float4*)&wv[(size_t)(c0 + lw_c) * D_ + d0 + lw_k];
        sW[lw_c][lw_k + 0] = w4.x; sW[lw_c][lw_k + 1] = w4.y;
        sW[lw_c][lw_k + 2] = w4.z; sW[lw_c][lw_k + 3] = w4.w;
#pragma unroll
        for (int r = 0; r < 4; r++) {
            int e = r * 256 + tx;
            int bb = e >> 5, d = e & 31;
            size_t idx = (size_t)(bb * H_ + h) * D_ + d0 + d;
            sC[d][bb] = g_ctx[0][idx] + g_ctx[1][idx] + g_ctx[2][idx] + g_ctx[3][idx];
        }
        __syncthreads();
#pragma unroll
        for (int d = 0; d < 32; d++) {
            float w = sW[col_l][d];
            float4 c4 = *(const float4*)&sC[d][bg * 4];
            acc[0] = fmaf(w, c4.x, acc[0]);
            acc[1] = fmaf(w, c4.y, acc[1]);
            acc[2] = fmaf(w, c4.z, acc[2]);
            acc[3] = fmaf(w, c4.w, acc[3]);
        }
    }
    float bias = bv[c0 + col_l];
#pragma unroll
    for (int i = 0; i < 4; i++)
        g_op[(size_t)(bg * 4 + i) * D_ + c0 + col_l] = acc[i] + bias;
}

// ==================== host ====================
static void gemmSK(const float* A, int lda, const float* W, int Ktot,
                   const float* bias, float* out, int ldo,
                   int C, int rows, int Z, int act, int accflag) {
    void* pp = nullptr;
    cudaGetSymbolAddress(&pp, g_part);
    k_gemmKS<<<dim3(C / 32, rows / 32, Z), 256>>>(A, lda, W, Ktot, (float*)pp, C, rows, Ktot / Z);
    k_gemmEp<<<(rows * C + 255) / 256, 256>>>(Z, rows, C, bias, out, ldo, act, accflag);
}

static float* devptr(const void* sym) {
    void* p = nullptr;
    cudaGetSymbolAddress(&p, (const void*)sym);
    return (float*)p;
}

extern "C" void kernel_launch(void* const* d_in, const int* in_sizes, int n_in,
                              void* d_out, int out_size) {
    const float* frame    = (const float*)d_in[0];
    const float* kvsal    = (const float*)d_in[1];
    const float* max_init = (const float*)d_in[2];
    const float* qbase    = (const float*)d_in[3];
    const float* role     = (const float*)d_in[4];
    const float* timew    = (const float*)d_in[5];
    const float* ln1_g = (const float*)d_in[6],  *ln1_b = (const float*)d_in[7];
    const float* sa_in_w = (const float*)d_in[8],  *sa_in_b = (const float*)d_in[9];
    const float* sa_out_w = (const float*)d_in[10], *sa_out_b = (const float*)d_in[11];
    const float* ln2_g = (const float*)d_in[12], *ln2_b = (const float*)d_in[13];
    const float* cg_in_w = (const float*)d_in[14], *cg_in_b = (const float*)d_in[15];
    const float* cg_out_w = (const float*)d_in[16], *cg_out_b = (const float*)d_in[17];
    const float* cs_in_w = (const float*)d_in[18], *cs_in_b = (const float*)d_in[19];
    const float* cs_out_w = (const float*)d_in[20], *cs_out_b = (const float*)d_in[21];
    const float* ln3_g = (const float*)d_in[22], *ln3_b = (const float*)d_in[23];
    const float* ffn_w1 = (const float*)d_in[24], *ffn_b1 = (const float*)d_in[25];
    const float* ffn_w2 = (const float*)d_in[26], *ffn_b2 = (const float*)d_in[27];
    const float* out_g = (const float*)d_in[28], *out_b = (const float*)d_in[29];
    const int* fidx = (const int*)d_in[30];
    float* out = (float*)d_out;

    float* dq    = devptr(g_q);
    float* dx    = devptr(g_x);
    float* dqn   = devptr(g_qn);
    float* dqkv  = devptr(g_qkv);
    float* dattn = devptr(g_attn);
    float* dqp   = devptr(g_qp);
    float* dop   = devptr(g_op);
    float* dffn  = devptr(g_ffn);

    // ---- init ----
    k_meanpart<<<dim3(B_, 4, 4), 256>>>(frame);
    k_qinit<<<dim3(B_, 4), 256>>>(max_init, qbase, role, timew, fidx);

    for (int l = 0; l < 2; l++) {
        const float* saw  = sa_in_w  + (size_t)l * 3 * D_ * D_;
        const float* sab  = sa_in_b  + (size_t)l * 3 * D_;
        const float* saow = sa_out_w + (size_t)l * D_ * D_;
        const float* saob = sa_out_b + (size_t)l * D_;

        // --- self-attention block ---
        k_ln<<<64, 256>>>(dq, dx, ln1_g + l * D_, ln1_b + l * D_);
        gemmSK(dx, D_, saw, D_, sab, dqkv, 3 * D_, 3 * D_, 64, 8, 0, 0);
        k_selfattn<<<dim3(B_, H_), 32>>>();
        gemmSK(dattn, D_, saow, D_, saob, dq, D_, D_, 64, 8, 0, 1);

        // --- LN2 ---
        k_ln<<<64, 256>>>(dq, dqn, ln2_g + l * D_, ln2_b + l * D_);

        // --- cross-attention stream A (token 0, frame_tokens, N=4096) ---
        {
            const float* cw  = cg_in_w  + (size_t)l * 3 * D_ * D_;
            const float* cb  = cg_in_b  + (size_t)l * 3 * D_;
            const float* cow = cg_out_w + (size_t)l * D_ * D_;
            const float* cob = cg_out_b + (size_t)l * D_;
            gemmSK(dqn, 2 * D_, cw, D_, cb, dqp, D_, D_, 32, 8, 0, 0);
            k_qkdir<<<dim3(H_, 4, 4), 256>>>(dqp, cw + (size_t)D_ * D_);
            k_scores<<<dim3(N_ / 128, B_), 128>>>(frame, N_);
            k_softmax<<<B_ * H_, 256>>>(N_);
            k_context<<<dim3(4, B_, 4), 128>>>(frame, N_);
            k_vproj<<<32, 256>>>(cw + (size_t)2 * D_ * D_, cb + 2 * D_);
            gemmSK(dop, D_, cow, D_, cob, dq, 2 * D_, D_, 32, 8, 0, 1);
        }
        // --- cross-attention stream B (token 1, kv_salient, K=1024) ---
        {
            const float* cw  = cs_in_w  + (size_t)l * 3 * D_ * D_;
            const float* cb  = cs_in_b  + (size_t)l * 3 * D_;
            const float* cow = cs_out_w + (size_t)l * D_ * D_;
            const float* cob = cs_out_b + (size_t)l * D_;
            gemmSK(dqn + D_, 2 * D_, cw, D_, cb, dqp, D_, D_, 32, 8, 0, 0);
            k_qkdir<<<dim3(H_, 4, 4), 256>>>(dqp, cw + (size_t)D_ * D_);
            k_scores<<<dim3(KS_ / 128, B_), 128>>>(kvsal, KS_);
            k_softmax<<<B_ * H_, 256>>>(KS_);
            k_context<<<dim3(4, B_, 4), 128>>>(kvsal, KS_);
            k_vproj<<<32, 256>>>(cw + (size_t)2 * D_ * D_, cb + 2 * D_);
            gemmSK(dop, D_, cow, D_, cob, dq + D_, 2 * D_, D_, 32, 8, 0, 1);
        }

        // --- FFN ---
        k_ln<<<64, 256>>>(dq, dx, ln3_g + l * D_, ln3_b + l * D_);
        gemmSK(dx, D_, ffn_w1 + (size_t)l * 4 * D_ * D_, D_,
               ffn_b1 + (size_t)l * 4 * D_, dffn, 4 * D_, 4 * D_, 64, 4, 1, 0);
        gemmSK(dffn, 4 * D_, ffn_w2 + (size_t)l * 4 * D_ * D_, 4 * D_,
               ffn_b2 + (size_t)l * D_, dq, D_, D_, 64, 8, 0, 1);
    }

    // ---- final LN ----
    k_ln<<<64, 256>>>(dq, out, out_g, out_b);
}

// round 16
// speedup vs baseline: 1.1640x; 1.0358x over previous
#include <cuda_runtime.h>
#include <math.h>

#define B_ 32
#define N_ 4096
#define KS_ 1024
#define D_ 1024
#define H_ 16
#define MAXF_ 4096
#define CTXM (B_*H_*D_)

typedef unsigned long long u64;

__device__ __forceinline__ void fma2(u64 &d, u64 a, u64 b) {
    asm("fma.rn.f32x2 %0,%1,%2,%0;" : "+l"(d) : "l"(a), "l"(b));
}
__device__ __forceinline__ void lds128(u64 &a, u64 &b, const void* p) {
    unsigned s = (unsigned)__cvta_generic_to_shared(p);
    asm("ld.shared.v2.u64 {%0,%1},[%2];" : "=l"(a), "=l"(b) : "r"(s));
}
__device__ __forceinline__ float2 unpk(u64 v) {
    float2 r; asm("mov.b64 {%0,%1},%2;" : "=f"(r.x), "=f"(r.y) : "l"(v)); return r;
}
__device__ __forceinline__ u64 dup2(float x) {
    u64 r; asm("mov.b64 %0,{%1,%1};" : "=l"(r) : "f"(x)); return r;
}

// ---------------- scratch (device globals; no allocation) ----------------
__device__ float g_q[B_*2*D_];
__device__ float g_x[B_*2*D_];
__device__ float g_qn[B_*2*D_];
__device__ float g_qkv[B_*2*3*D_];
__device__ float g_attn[B_*2*D_];
__device__ float g_qp[B_*D_];
__device__ float g_qkd[B_*H_*D_];
__device__ float g_S[(size_t)B_*H_*N_];
__device__ float g_ctx[8][CTXM];
__device__ float g_op[B_*D_];
__device__ float g_ffn[B_*2*4*D_];
__device__ float g_mp[4][B_*D_];
__device__ float g_part[2*1024*1024];

// ---------------- partial mean over N (4 k-segments) ----------------
__global__ void k_meanpart(const float* __restrict__ frame) {
    int b = blockIdx.x, dc = blockIdx.y, ks = blockIdx.z;
    int d = dc * 256 + threadIdx.x;
    const float* p = frame + ((size_t)b * N_ + (size_t)ks * (N_ / 4)) * D_ + d;
    float s = 0.f;
#pragma unroll 8
    for (int k = 0; k < N_ / 4; k++) s += p[(size_t)k * D_];
    g_mp[ks][b * D_ + d] = s;
}

// ---------------- q init ----------------
__global__ void k_qinit(const float* __restrict__ max_init,
                        const float* __restrict__ qbase,
                        const float* __restrict__ role,
                        const float* __restrict__ timew,
                        const int* __restrict__ fidx) {
    int b = blockIdx.x;
    int d = blockIdx.y * 256 + threadIdx.x;
    int fi = fidx[b];
    fi = fi < 0 ? 0 : (fi > MAXF_ - 1 ? MAXF_ - 1 : fi);
    float te = timew[(size_t)fi * D_ + d];
    float mean = (g_mp[0][b * D_ + d] + g_mp[1][b * D_ + d] +
                  g_mp[2][b * D_ + d] + g_mp[3][b * D_ + d]) * (1.f / N_);
    g_q[(size_t)(b * 2 + 0) * D_ + d] = mean + qbase[d] + role[d] + te;
    g_q[(size_t)(b * 2 + 1) * D_ + d] = max_init[(size_t)b * D_ + d] + qbase[D_ + d] + role[D_ + d] + te;
}

// ---------------- layernorm (one block per row) ----------------
__global__ void k_ln(const float* __restrict__ in, float* __restrict__ out,
                     const float* __restrict__ g, const float* __restrict__ bta) {
    __shared__ float sh[8];
    __shared__ float stat[2];
    int r = blockIdx.x;
    const float* x = in + (size_t)r * D_;
    float s = 0.f;
    for (int i = threadIdx.x; i < D_; i += 256) s += x[i];
#pragma unroll
    for (int o = 16; o > 0; o >>= 1) s += __shfl_xor_sync(0xffffffffu, s, o);
    if ((threadIdx.x & 31) == 0) sh[threadIdx.x >> 5] = s;
    __syncthreads();
    if (threadIdx.x == 0) {
        float t = 0.f;
        for (int i = 0; i < 8; i++) t += sh[i];
        stat[0] = t * (1.f / D_);
    }
    __syncthreads();
    float mean = stat[0];
    float v = 0.f;
    for (int i = threadIdx.x; i < D_; i += 256) { float t = x[i] - mean; v += t * t; }
#pragma unroll
    for (int o = 16; o > 0; o >>= 1) v += __shfl_xor_sync(0xffffffffu, v, o);
    if ((threadIdx.x & 31) == 0) sh[threadIdx.x >> 5] = v;
    __syncthreads();
    if (threadIdx.x == 0) {
        float t = 0.f;
        for (int i = 0; i < 8; i++) t += sh[i];
        stat[1] = rsqrtf(t * (1.f / D_) + 1e-5f);
    }
    __syncthreads();
    float rstd = stat[1];
    for (int i = threadIdx.x; i < D_; i += 256)
        out[(size_t)r * D_ + i] = (x[i] - mean) * rstd * g[i] + bta[i];
}

// ---------------- split-K skinny GEMM ----------------
__global__ void __launch_bounds__(256) k_gemmKS(
        const float* __restrict__ A, int lda,
        const float* __restrict__ W, int Ktot,
        float* __restrict__ part, int C, int rowsTot, int Kslice) {
    __shared__ float sW[32][33];
    __shared__ float sA[32][36];
    int z = blockIdx.z;
    int col_l = threadIdx.x & 31;
    int rg = threadIdx.x >> 5;
    int c = blockIdx.x * 32 + col_l;
    int r0 = blockIdx.y * 32;
    float accv[4] = {0.f, 0.f, 0.f, 0.f};
    int lw_c = threadIdx.x >> 3;
    int lw_k = (threadIdx.x & 7) * 4;
    int kstart = z * Kslice;
    for (int k0 = kstart; k0 < kstart + Kslice; k0 += 32) {
        __syncthreads();
        float4 wv = *(const float4*)&W[(size_t)(blockIdx.x * 32 + lw_c) * Ktot + k0 + lw_k];
        sW[lw_c][lw_k + 0] = wv.x; sW[lw_c][lw_k + 1] = wv.y;
        sW[lw_c][lw_k + 2] = wv.z; sW[lw_c][lw_k + 3] = wv.w;
        float4 av = *(const float4*)&A[(size_t)(r0 + lw_c) * lda + k0 + lw_k];
        sA[lw_k + 0][lw_c] = av.x; sA[lw_k + 1][lw_c] = av.y;
        sA[lw_k + 2][lw_c] = av.z; sA[lw_k + 3][lw_c] = av.w;
        __syncthreads();
#pragma unroll
        for (int k = 0; k < 32; k++) {
            float w = sW[col_l][k];
            float4 a = *(const float4*)&sA[k][rg * 4];
            accv[0] = fmaf(a.x, w, accv[0]);
            accv[1] = fmaf(a.y, w, accv[1]);
            accv[2] = fmaf(a.z, w, accv[2]);
            accv[3] = fmaf(a.w, w, accv[3]);
        }
    }
#pragma unroll
    for (int i = 0; i < 4; i++)
        part[((size_t)(z * rowsTot + r0 + rg * 4 + i)) * C + c] = accv[i];
}

// ---------------- GEMM epilogue ----------------
__global__ void k_gemmEp(int Z, int rowsTot, int C,
                         const float* __restrict__ bias,
                         float* __restrict__ out, int ldo, int act, int accflag) {
    int idx = blockIdx.x * 256 + threadIdx.x;
    if (idx >= rowsTot * C) return;
    int r = idx / C, c = idx - r * C;
    float s = 0.f;
    for (int z = 0; z < Z; z++) s += g_part[((size_t)(z * rowsTot + r)) * C + c];
    s += bias[c];
    if (act == 1) s = 0.5f * s * (1.f + erff(s * 0.70710678118654752f));
    float* o = &out[(size_t)r * ldo + c];
    if (accflag) *o += s; else *o = s;
}

// ---------------- self-attention over 2 tokens ----------------
__global__ void k_selfattn() {
    int b = blockIdx.x, h = blockIdx.y, lane = threadIdx.x;
    const float* row0 = g_qkv + (size_t)(b * 2 + 0) * 3072;
    const float* row1 = g_qkv + (size_t)(b * 2 + 1) * 3072;
    int off = h * 64 + lane * 2;
    float2 q0 = *(const float2*)(row0 + off);
    float2 q1 = *(const float2*)(row1 + off);
    float2 kk0 = *(const float2*)(row0 + 1024 + off);
    float2 kk1 = *(const float2*)(row1 + 1024 + off);
    float2 v0 = *(const float2*)(row0 + 2048 + off);
    float2 v1 = *(const float2*)(row1 + 2048 + off);
    float s00 = q0.x * kk0.x + q0.y * kk0.y;
    float s01 = q0.x * kk1.x + q0.y * kk1.y;
    float s10 = q1.x * kk0.x + q1.y * kk0.y;
    float s11 = q1.x * kk1.x + q1.y * kk1.y;
#pragma unroll
    for (int o = 16; o > 0; o >>= 1) {
        s00 += __shfl_xor_sync(0xffffffffu, s00, o);
        s01 += __shfl_xor_sync(0xffffffffu, s01, o);
        s10 += __shfl_xor_sync(0xffffffffu, s10, o);
        s11 += __shfl_xor_sync(0xffffffffu, s11, o);
    }
    s00 *= 0.125f; s01 *= 0.125f; s10 *= 0.125f; s11 *= 0.125f;
    float m0 = fmaxf(s00, s01), m1 = fmaxf(s10, s11);
    float e00 = expf(s00 - m0), e01 = expf(s01 - m0);
    float e10 = expf(s10 - m1), e11 = expf(s11 - m1);
    float i0 = 1.f / (e00 + e01), i1 = 1.f / (e10 + e11);
    float a00 = e00 * i0, a01 = e01 * i0, a10 = e10 * i1, a11 = e11 * i1;
    float2 o0, o1;
    o0.x = a00 * v0.x + a01 * v1.x; o0.y = a00 * v0.y + a01 * v1.y;
    o1.x = a10 * v0.x + a11 * v1.x; o1.y = a10 * v0.y + a11 * v1.y;
    *(float2*)(g_attn + (size_t)(b * 2 + 0) * D_ + off) = o0;
    *(float2*)(g_attn + (size_t)(b * 2 + 1) * D_ + off) = o1;
}

// ---------------- qkdir ----------------
__global__ void k_qkdir(const float* __restrict__ qp, const float* __restrict__ wk) {
    int h = blockIdx.x;
    int d = blockIdx.y * 256 + threadIdx.x;
    int b0 = blockIdx.z * 8;
    __shared__ float sqp[8][64];
    for (int i = threadIdx.x; i < 512; i += 256) {
        int bb = i >> 6, j = i & 63;
        sqp[bb][j] = qp[(size_t)(b0 + bb) * D_ + h * 64 + j];
    }
    __syncthreads();
    float acc[8] = {0.f, 0.f, 0.f, 0.f, 0.f, 0.f, 0.f, 0.f};
    const float* wp = wk + (size_t)(h * 64) * D_ + d;
#pragma unroll 4
    for (int j = 0; j < 64; j++) {
        float w = wp[(size_t)j * D_];
#pragma unroll
        for (int bb = 0; bb < 8; bb++) acc[bb] = fmaf(sqp[bb][j], w, acc[bb]);
    }
#pragma unroll
    for (int bb = 0; bb < 8; bb++)
        g_qkd[(size_t)((b0 + bb) * H_ + h) * D_ + d] = acc[bb];
}

// ---------------- scores: 8h x 8k register tile, FFMA2 packed over d ----------
// grid (Nk/256, B); block 64 (2 warps); warp = head-group, lane = key slot
__global__ void __launch_bounds__(64) k_scores(const float* __restrict__ f, int Nk) {
    __shared__ float sf[256][36];
    __shared__ float sq[16][36];
    int b = blockIdx.y;
    int k0 = blockIdx.x * 256;
    int tx = threadIdx.x;
    int hg = tx >> 5;          // 0..1 -> heads hg*8..+7
    int kg = tx & 31;          // keys kg + 32*i
    u64 acc[8][8];
#pragma unroll
    for (int i = 0; i < 8; i++)
#pragma unroll
        for (int j = 0; j < 8; j++) acc[i][j] = 0ull;
    const float* fb = f + ((size_t)b * Nk + k0) * D_;
    const float* qb = g_qkd + (size_t)b * H_ * D_;
    for (int d0 = 0; d0 < D_; d0 += 32) {
        __syncthreads();
        for (int e = tx; e < 512; e += 64) {
            int h = e >> 5, d = e & 31;
            sq[h][d] = qb[(size_t)h * D_ + d0 + d];
        }
#pragma unroll
        for (int i = 0; i < 32; i++) {
            int e4 = tx + i * 64;
            int key = e4 >> 3;
            int dd = (e4 & 7) * 4;
            *(float4*)&sf[key][dd] = *(const float4*)(fb + (size_t)key * D_ + d0 + dd);
        }
        __syncthreads();
#pragma unroll
        for (int dp = 0; dp < 8; dp++) {
            int d = dp * 4;
            u64 fk[8][2];
#pragma unroll
            for (int i = 0; i < 8; i++)
                lds128(fk[i][0], fk[i][1], &sf[kg + 32 * i][d]);
#pragma unroll
            for (int hh = 0; hh < 8; hh++) {
                u64 q0, q1;
                lds128(q0, q1, &sq[hg * 8 + hh][d]);
#pragma unroll
                for (int i = 0; i < 8; i++) {
                    fma2(acc[hh][i], q0, fk[i][0]);
                    fma2(acc[hh][i], q1, fk[i][1]);
                }
            }
        }
    }
#pragma unroll
    for (int hh = 0; hh < 8; hh++) {
        int h = hg * 8 + hh;
#pragma unroll
        for (int i = 0; i < 8; i++) {
            float2 t = unpk(acc[hh][i]);
            g_S[((size_t)b * H_ + h) * Nk + k0 + kg + 32 * i] = (t.x + t.y) * 0.125f;
        }
    }
}

// ---------------- softmax over Nk per (b,h) row ----------
__global__ void k_softmax(int Nk) {
    __shared__ float sh[8];
    __shared__ float stat;
    int tx = threadIdx.x;
    float* s = g_S + (size_t)blockIdx.x * Nk;
    float m = -1e30f;
    for (int i = tx; i < Nk; i += 256) m = fmaxf(m, s[i]);
#pragma unroll
    for (int o = 16; o > 0; o >>= 1) m = fmaxf(m, __shfl_xor_sync(0xffffffffu, m, o));
    if ((tx & 31) == 0) sh[tx >> 5] = m;
    __syncthreads();
    if (tx == 0) {
        float t = sh[0];
        for (int i = 1; i < 8; i++) t = fmaxf(t, sh[i]);
        stat = t;
    }
    __syncthreads();
    m = stat;
    float sum = 0.f;
    for (int i = tx; i < Nk; i += 256) {
        float e = expf(s[i] - m);
        s[i] = e;
        sum += e;
    }
#pragma unroll
    for (int o = 16; o > 0; o >>= 1) sum += __shfl_xor_sync(0xffffffffu, sum, o);
    if ((tx & 31) == 0) sh[tx >> 5] = sum;
    __syncthreads();
    if (tx == 0) {
        float t = 0.f;
        for (int i = 0; i < 8; i++) t += sh[i];
        stat = 1.f / t;
    }
    __syncthreads();
    float inv = stat;
    for (int i = tx; i < Nk; i += 256) s[i] *= inv;
}

// ---------------- context: broadcast-a + 8h x 16d tile, FFMA2 over d ----------
// grid (B, parts); block 128 (4 warps); warp covers 8 heads x 512 d
__global__ void __launch_bounds__(128) k_context(const float* __restrict__ f,
                                                 int Nk, int kn) {
    __shared__ float sf[8][1040];
    __shared__ float sa[8][16];
    int b = blockIdx.x;
    int part = blockIdx.y;
    int tx = threadIdx.x;
    int w = tx >> 5, lane = tx & 31;
    int hs = (w & 1) * 8;                 // head start
    int dbase = (w >> 1) * 512 + lane * 4; // + j*128
    u64 acc[8][8];
#pragma unroll
    for (int i = 0; i < 8; i++)
#pragma unroll
        for (int j = 0; j < 8; j++) acc[i][j] = 0ull;
    const float* fb = f + ((size_t)b * Nk + (size_t)part * kn) * D_;
    const float* ab = g_S + (size_t)b * H_ * Nk + (size_t)part * kn;
    for (int kc = 0; kc < kn; kc += 8) {
        __syncthreads();
        if (tx < 128) {
            int kk = tx >> 4, h = tx & 15;
            sa[kk][h] = ab[(size_t)h * Nk + kc + kk];
        }
#pragma unroll
        for (int i = 0; i < 16; i++) {
            int e4 = tx + i * 128;
            int kk = e4 >> 8;
            int du = (e4 & 255) * 4;
            *(float4*)&sf[kk][du] = *(const float4*)(fb + (size_t)(kc + kk) * D_ + du);
        }
        __syncthreads();
#pragma unroll
        for (int kk = 0; kk < 8; kk++) {
            float4 a0 = *(const float4*)&sa[kk][hs];
            float4 a1 = *(const float4*)&sa[kk][hs + 4];
            u64 ad[8];
            ad[0] = dup2(a0.x); ad[1] = dup2(a0.y); ad[2] = dup2(a0.z); ad[3] = dup2(a0.w);
            ad[4] = dup2(a1.x); ad[5] = dup2(a1.y); ad[6] = dup2(a1.z); ad[7] = dup2(a1.w);
            u64 fv[8];
#pragma unroll
            for (int j = 0; j < 4; j++)
                lds128(fv[2 * j], fv[2 * j + 1], &sf[kk][dbase + j * 128]);
#pragma unroll
            for (int hh = 0; hh < 8; hh++)
#pragma unroll
                for (int j = 0; j < 8; j++)
                    fma2(acc[hh][j], ad[hh], fv[j]);
        }
    }
#pragma unroll
    for (int hh = 0; hh < 8; hh++) {
#pragma unroll
        for (int j = 0; j < 4; j++) {
            size_t idx = (size_t)(b * H_ + hs + hh) * D_ + dbase + j * 128;
            *(u64*)&g_ctx[part][idx] = acc[hh][2 * j];
            *(u64*)&g_ctx[part][idx + 2] = acc[hh][2 * j + 1];
        }
    }
}

// ---------------- vproj (np split-parts) ----------------
__global__ void k_vproj(const float* __restrict__ wv, const float* __restrict__ bv, int np) {
    int c0 = blockIdx.x * 32;
    int h = c0 >> 6;
    int tx = threadIdx.x;
    int col_l = tx & 31, bg = tx >> 5;
    __shared__ float sW[32][33];
    __shared__ float sC[32][36];
    float acc[4] = {0.f, 0.f, 0.f, 0.f};
    int lw_c = tx >> 3, lw_k = (tx & 7) * 4;
    for (int d0 = 0; d0 < D_; d0 += 32) {
        __syncthreads();
        float4 w4 = *(const float4*)&wv[(size_t)(c0 + lw_c) * D_ + d0 + lw_k];
        sW[lw_c][lw_k + 0] = w4.x; sW[lw_c][lw_k + 1] = w4.y;
        sW[lw_c][lw_k + 2] = w4.z; sW[lw_c][lw_k + 3] = w4.w;
#pragma unroll
        for (int r = 0; r < 4; r++) {
            int e = r * 256 + tx;
            int bb = e >> 5, d = e & 31;
            size_t idx = (size_t)(bb * H_ + h) * D_ + d0 + d;
            float s = 0.f;
            for (int p = 0; p < np; p++) s += g_ctx[p][idx];
            sC[d][bb] = s;
        }
        __syncthreads();
#pragma unroll
        for (int d = 0; d < 32; d++) {
            float w = sW[col_l][d];
            float4 c4 = *(const float4*)&sC[d][bg * 4];
            acc[0] = fmaf(w, c4.x, acc[0]);
            acc[1] = fmaf(w, c4.y, acc[1]);
            acc[2] = fmaf(w, c4.z, acc[2]);
            acc[3] = fmaf(w, c4.w, acc[3]);
        }
    }
    float bias = bv[c0 + col_l];
#pragma unroll
    for (int i = 0; i < 4; i++)
        g_op[(size_t)(bg * 4 + i) * D_ + c0 + col_l] = acc[i] + bias;
}

// ==================== host ====================
static void gemmSK(const float* A, int lda, const float* W, int Ktot,
                   const float* bias, float* out, int ldo,
                   int C, int rows, int Z, int act, int accflag) {
    void* pp = nullptr;
    cudaGetSymbolAddress(&pp, g_part);
    k_gemmKS<<<dim3(C / 32, rows / 32, Z), 256>>>(A, lda, W, Ktot, (float*)pp, C, rows, Ktot / Z);
    k_gemmEp<<<(rows * C + 255) / 256, 256>>>(Z, rows, C, bias, out, ldo, act, accflag);
}

static float* devptr(const void* sym) {
    void* p = nullptr;
    cudaGetSymbolAddress(&p, (const void*)sym);
    return (float*)p;
}

extern "C" void kernel_launch(void* const* d_in, const int* in_sizes, int n_in,
                              void* d_out, int out_size) {
    const float* frame    = (const float*)d_in[0];
    const float* kvsal    = (const float*)d_in[1];
    const float* max_init = (const float*)d_in[2];
    const float* qbase    = (const float*)d_in[3];
    const float* role     = (const float*)d_in[4];
    const float* timew    = (const float*)d_in[5];
    const float* ln1_g = (const float*)d_in[6],  *ln1_b = (const float*)d_in[7];
    const float* sa_in_w = (const float*)d_in[8],  *sa_in_b = (const float*)d_in[9];
    const float* sa_out_w = (const float*)d_in[10], *sa_out_b = (const float*)d_in[11];
    const float* ln2_g = (const float*)d_in[12], *ln2_b = (const float*)d_in[13];
    const float* cg_in_w = (const float*)d_in[14], *cg_in_b = (const float*)d_in[15];
    const float* cg_out_w = (const float*)d_in[16], *cg_out_b = (const float*)d_in[17];
    const float* cs_in_w = (const float*)d_in[18], *cs_in_b = (const float*)d_in[19];
    const float* cs_out_w = (const float*)d_in[20], *cs_out_b = (const float*)d_in[21];
    const float* ln3_g = (const float*)d_in[22], *ln3_b = (const float*)d_in[23];
    const float* ffn_w1 = (const float*)d_in[24], *ffn_b1 = (const float*)d_in[25];
    const float* ffn_w2 = (const float*)d_in[26], *ffn_b2 = (const float*)d_in[27];
    const float* out_g = (const float*)d_in[28], *out_b = (const float*)d_in[29];
    const int* fidx = (const int*)d_in[30];
    float* out = (float*)d_out;

    float* dq    = devptr(g_q);
    float* dx    = devptr(g_x);
    float* dqn   = devptr(g_qn);
    float* dattn = devptr(g_attn);
    float* dqkv  = devptr(g_qkv);
    float* dqp   = devptr(g_qp);
    float* dop   = devptr(g_op);
    float* dffn  = devptr(g_ffn);

    // ---- init ----
    k_meanpart<<<dim3(B_, 4, 4), 256>>>(frame);
    k_qinit<<<dim3(B_, 4), 256>>>(max_init, qbase, role, timew, fidx);

    for (int l = 0; l < 2; l++) {
        const float* saw  = sa_in_w  + (size_t)l * 3 * D_ * D_;
        const float* sab  = sa_in_b  + (size_t)l * 3 * D_;
        const float* saow = sa_out_w + (size_t)l * D_ * D_;
        const float* saob = sa_out_b + (size_t)l * D_;

        // --- self-attention block ---
        k_ln<<<64, 256>>>(dq, dx, ln1_g + l * D_, ln1_b + l * D_);
        gemmSK(dx, D_, saw, D_, sab, dqkv, 3 * D_, 3 * D_, 64, 8, 0, 0);
        k_selfattn<<<dim3(B_, H_), 32>>>();
        gemmSK(dattn, D_, saow, D_, saob, dq, D_, D_, 64, 8, 0, 1);

        // --- LN2 ---
        k_ln<<<64, 256>>>(dq, dqn, ln2_g + l * D_, ln2_b + l * D_);

        // --- cross-attention stream A (token 0, frame_tokens, N=4096) ---
        {
            const float* cw  = cg_in_w  + (size_t)l * 3 * D_ * D_;
            const float* cb  = cg_in_b  + (size_t)l * 3 * D_;
            const float* cow = cg_out_w + (size_t)l * D_ * D_;
            const float* cob = cg_out_b + (size_t)l * D_;
            gemmSK(dqn, 2 * D_, cw, D_, cb, dqp, D_, D_, 32, 8, 0, 0);
            k_qkdir<<<dim3(H_, 4, 4), 256>>>(dqp, cw + (size_t)D_ * D_);
            k_scores<<<dim3(N_ / 256, B_), 64>>>(frame, N_);
            k_softmax<<<B_ * H_, 256>>>(N_);
            k_context<<<dim3(B_, 8), 128>>>(frame, N_, N_ / 8);
            k_vproj<<<32, 256>>>(cw + (size_t)2 * D_ * D_, cb + 2 * D_, 8);
            gemmSK(dop, D_, cow, D_, cob, dq, 2 * D_, D_, 32, 8, 0, 1);
        }
        // --- cross-attention stream B (token 1, kv_salient, K=1024) ---
        {
            const float* cw  = cs_in_w  + (size_t)l * 3 * D_ * D_;
            const float* cb  = cs_in_b  + (size_t)l * 3 * D_;
            const float* cow = cs_out_w + (size_t)l * D_ * D_;
            const float* cob = cs_out_b + (size_t)l * D_;
            gemmSK(dqn + D_, 2 * D_, cw, D_, cb, dqp, D_, D_, 32, 8, 0, 0);
            k_qkdir<<<dim3(H_, 4, 4), 256>>>(dqp, cw + (size_t)D_ * D_);
            k_scores<<<dim3(KS_ / 256, B_), 64>>>(kvsal, KS_);
            k_softmax<<<B_ * H_, 256>>>(KS_);
            k_context<<<dim3(B_, 4), 128>>>(kvsal, KS_, KS_ / 4);
            k_vproj<<<32, 256>>>(cw + (size_t)2 * D_ * D_, cb + 2 * D_, 4);
            gemmSK(dop, D_, cow, D_, cob, dq + D_, 2 * D_, D_, 32, 8, 0, 1);
        }

        // --- FFN ---
        k_ln<<<64, 256>>>(dq, dx, ln3_g + l * D_, ln3_b + l * D_);
        gemmSK(dx, D_, ffn_w1 + (size_t)l * 4 * D_ * D_, D_,
               ffn_b1 + (size_t)l * 4 * D_, dffn, 4 * D_, 4 * D_, 64, 4, 1, 0);
        gemmSK(dffn, 4 * D_, ffn_w2 + (size_t)l * 4 * D_ * D_, 4 * D_,
               ffn_b2 + (size_t)l * D_, dq, D_, D_, 64, 8, 0, 1);
    }

    // ---- final LN ----
    k_ln<<<64, 256>>>(dq, out, out_g, out_b);
}